// round 13
// baseline (speedup 1.0000x reference)
#include <cuda_runtime.h>
#include <cuda_fp16.h>
#include <stdint.h>
#include <math.h>

// ---------------- dims ----------------
#define HD 512
#define BD 512
#define TD 128

#define MB 64        // batch rows per CTA (M)
#define NU 32        // units per CTA; N = 4 gates x 32 = 128
#define KC 64        // k per stage

// smem stage layout: rows padded to 144B (64 fp16 = 128B data + 16B pad)
#define ROWB 144
#define A_BYTES (64 * ROWB)                 // 9216
#define W_BYTES (128 * ROWB)                // 18432
#define OFF_W A_BYTES
#define STAGE_BYTES (A_BYTES + W_BYTES)     // 27648
#define NSTG 4
#define OFF_XS (NSTG * STAGE_BYTES)         // 110592
#define SMEM_TOTAL (OFF_XS + 1024)          // 111616

// ---------------- persistent device state ----------------
__device__ float g_c1[BD*HD];
__device__ float g_c2[BD*HD];
__device__ float g_h2f[2][BD*HD];
__device__ __align__(16) __half g_h1q[2][BD*HD];
__device__ __align__(16) __half g_h2q[2][BD*HD];
__device__ float g_b0[4*HD], g_b1[4*HD];
__device__ __align__(16) __half g_whh0[4*HD*HD];
__device__ __align__(16) __half g_wih1[4*HD*HD];
__device__ __align__(16) __half g_whh1[4*HD*HD];

// ---------------- helpers ----------------
__device__ __forceinline__ uint32_t smem_u32(const void* p) {
    uint32_t a;
    asm("{ .reg .u64 t; cvta.to.shared.u64 t, %1; cvt.u32.u64 %0, t; }" : "=r"(a) : "l"(p));
    return a;
}
__device__ __forceinline__ void cpa16(uint32_t dst, const void* src) {
    asm volatile("cp.async.cg.shared.global [%0], [%1], 16;" :: "r"(dst), "l"(src));
}
#define CP_COMMIT() asm volatile("cp.async.commit_group;")
#define CP_WAIT(n)  asm volatile("cp.async.wait_group %0;" :: "n"(n))

__device__ __forceinline__ void ldm4(uint32_t (&r)[4], uint32_t addr) {
    asm volatile("ldmatrix.sync.aligned.m8n8.x4.shared.b16 {%0,%1,%2,%3}, [%4];"
        : "=r"(r[0]), "=r"(r[1]), "=r"(r[2]), "=r"(r[3]) : "r"(addr));
}
__device__ __forceinline__ void mma_f16(float (&d)[4], const uint32_t a[4], const uint32_t b[2]) {
    asm volatile("mma.sync.aligned.m16n8k16.row.col.f32.f16.f16.f32 "
        "{%0,%1,%2,%3}, {%4,%5,%6,%7}, {%8,%9}, {%0,%1,%2,%3};"
        : "+f"(d[0]), "+f"(d[1]), "+f"(d[2]), "+f"(d[3])
        : "r"(a[0]), "r"(a[1]), "r"(a[2]), "r"(a[3]), "r"(b[0]), "r"(b[1]));
}

__device__ __forceinline__ float sigf(float z) { return 1.0f / (1.0f + __expf(-z)); }
__device__ __forceinline__ float tanhsf(float z) {
    float e = __expf(2.0f * z);
    return 1.0f - 2.0f / (e + 1.0f);
}

// ---------------- stage loader: A 64xKC fp16, W 128xKC fp16 ----------------
__device__ __forceinline__ void stage_load(uint32_t st,
    const __half* __restrict__ a, const __half* __restrict__ w,
    int b0, int u0, int k0, int tid)
{
    #pragma unroll
    for (int q = 0; q < 2; q++) {
        int i = tid + q * 256;
        int r = i >> 3, s = (i & 7) * 8;           // s in fp16 elems (16B chunks)
        uint32_t doff = (uint32_t)(r * ROWB + s * 2);
        size_t goff = (size_t)(b0 + r) * HD + k0 + s;
        cpa16(st + doff, a + goff);
    }
    #pragma unroll
    for (int q = 0; q < 4; q++) {
        int i = tid + q * 256;
        int n = i >> 3, s = (i & 7) * 8;
        int wrow = ((n >> 5) << 9) + u0 + (n & 31);  // gate*512 + u
        uint32_t doff = (uint32_t)(n * ROWB + s * 2);
        size_t goff = (size_t)wrow * HD + k0 + s;
        cpa16(st + OFF_W + doff, w + goff);
    }
}

// ---------------- compute one 64-k stage: 1 product into d ----------------
__device__ __forceinline__ void compute_stage(uint32_t sbase, float (&d)[2][4][4],
                                              int wm, int wn, int lane)
{
    const int l7 = lane & 7, grp = lane >> 3;
    const uint32_t a_row = (uint32_t)(((grp & 1) << 3) + l7);
    const uint32_t a_kb  = (uint32_t)((grp >> 1) << 4);
    const uint32_t b_n   = (uint32_t)(((grp >> 1) << 3) + l7);
    const uint32_t b_kb  = (uint32_t)((grp & 1) << 4);

    #pragma unroll
    for (int kk = 0; kk < 4; kk++) {
        uint32_t kb = kk * 32;   // bytes: k16 step = 32B
        uint32_t Ah[2][4], Bh[2][4];
        #pragma unroll
        for (int mi = 0; mi < 2; mi++) {
            uint32_t ra = sbase + (wm * 32 + mi * 16 + a_row) * ROWB + kb + a_kb;
            ldm4(Ah[mi], ra);
        }
        #pragma unroll
        for (int p = 0; p < 2; p++) {
            uint32_t rb = sbase + OFF_W + (wn * 32 + p * 16 + b_n) * ROWB + kb + b_kb;
            ldm4(Bh[p], rb);
        }
        #pragma unroll
        for (int mi = 0; mi < 2; mi++) {
            #pragma unroll
            for (int ni = 0; ni < 4; ni++) {
                const uint32_t* bh = &Bh[ni >> 1][(ni & 1) * 2];
                mma_f16(d[mi][ni], Ah[mi], bh);
            }
        }
    }
}

// ---------------- accum -> smem gate buffer ----------------
__device__ __forceinline__ void store_gbuf(float* gbuf, float (&d)[2][4][4],
                                           int wm, int wn, int lane)
{
    const int gid = lane >> 2, tig = lane & 3;
    #pragma unroll
    for (int mi = 0; mi < 2; mi++) {
        #pragma unroll
        for (int ni = 0; ni < 4; ni++) {
            int row = wm * 32 + mi * 16 + gid;
            int c0 = wn * 32 + ni * 8 + tig * 2;
            gbuf[row * 132 + c0]           = d[mi][ni][0];
            gbuf[row * 132 + c0 + 1]       = d[mi][ni][1];
            gbuf[(row + 8) * 132 + c0]     = d[mi][ni][2];
            gbuf[(row + 8) * 132 + c0 + 1] = d[mi][ni][3];
        }
    }
}

// ---------------- 4-stage ring pipeline, one sync per stage ----------------
template<int NS>
__device__ __forceinline__ void run_pipeline(
    uint32_t sb,
    const __half* const* As, const __half* const* Ws,
    int b0, int u0, int tid,
    float (&d)[2][4][4], int wm, int wn, int lane)
{
    // stages 0,1 already preloaded by caller
    #pragma unroll 1
    for (int i = 0; i < NS; i++) {
        if (i + 2 < NS) {
            int j = i + 2, sg = j >> 3;
            stage_load(sb + (j % NSTG) * STAGE_BYTES, As[sg], Ws[sg],
                       b0, u0, (j & 7) * KC, tid);
            CP_COMMIT();
            CP_WAIT(2);
        } else {
            CP_WAIT(0);
        }
        __syncthreads();
        compute_stage(sb + (i % NSTG) * STAGE_BYTES, d, wm, wn, lane);
    }
    __syncthreads();   // protect gbuf aliasing of stage slots
}

// ---------------- setup kernels ----------------
__global__ void __launch_bounds__(256) zero_state() {
    int idx = blockIdx.x * 256 + threadIdx.x;   // grid 1024
    g_c1[idx] = 0.f; g_c2[idx] = 0.f;
    __half z = __float2half(0.f);
    g_h1q[0][idx] = z; g_h2q[0][idx] = z;
}
__global__ void __launch_bounds__(256) prep_bias(
    const float* __restrict__ b_ih0, const float* __restrict__ b_hh0,
    const float* __restrict__ b_ih1, const float* __restrict__ b_hh1) {
    int j = blockIdx.x * 256 + threadIdx.x;     // grid 8
    g_b0[j] = b_ih0[j] + b_hh0[j];
    g_b1[j] = b_ih1[j] + b_hh1[j];
}
// single fp16 weight quantization
__global__ void __launch_bounds__(256) quantw1(const float* __restrict__ w, int which) {
    __half* p;
    if (which == 0)      p = g_whh0;
    else if (which == 1) p = g_wih1;
    else                 p = g_whh1;
    int i = blockIdx.x * 256 + threadIdx.x;     // grid 4096
    p[i] = __float2half_rn(w[i]);
}

// ---------------- phase A: layer-0 step ----------------
__global__ void __launch_bounds__(256) phaseA_k(
    int rd, const float* __restrict__ xin, int t, int y_from_c2,
    const float* __restrict__ w_lin, const float* __restrict__ b_lin,
    float* __restrict__ out, int t_out, const float* __restrict__ w_ih0)
{
    extern __shared__ char sm[];
    uint32_t sb = smem_u32(sm);
    const int tid = threadIdx.x, lane = tid & 31, wid = tid >> 5;
    const int wm = wid >> 2, wn = wid & 3;
    const int b0 = blockIdx.x * MB, u0 = blockIdx.y * NU;
    float* xs = (float*)(sm + OFF_XS);

    const __half* As[2] = { g_h1q[rd], g_h1q[rd] };
    const __half* Ws[2] = { g_whh0, g_whh0 };

    // kick off pipeline fill FIRST so y/x work overlaps the loads
    stage_load(sb, As[0], Ws[0], b0, u0, 0, tid);
    CP_COMMIT();
    stage_load(sb + STAGE_BYTES, As[0], Ws[0], b0, u0, KC, tid);
    CP_COMMIT();

    // input scalar per batch row (teacher-forced or autoregressive)
    if (xin != nullptr) {
        if (tid < MB) xs[tid] = xin[(size_t)(b0 + tid) * TD + t];
    } else {
        const float* ysrc = y_from_c2 ? g_c2 : g_h2f[rd];
        int rrow = tid >> 2, p = tid & 3;
        const float4* hr = (const float4*)(ysrc + (size_t)(b0 + rrow) * HD);
        const float4* wl = (const float4*)w_lin;
        float s = 0.f;
        #pragma unroll 8
        for (int kk = p; kk < HD / 4; kk += 4) {
            float4 a = hr[kk]; float4 w = wl[kk];
            s += a.x * w.x + a.y * w.y + a.z * w.z + a.w * w.w;
        }
        s += __shfl_xor_sync(0xffffffffu, s, 1);
        s += __shfl_xor_sync(0xffffffffu, s, 2);
        if (p == 0) {
            float yv = s + b_lin[0];
            xs[rrow] = yv;
            if (blockIdx.y == 0) out[(size_t)(b0 + rrow) * TD + t_out] = yv;
        }
    }

    float d[2][4][4] = {};
    run_pipeline<8>(sb, As, Ws, b0, u0, tid, d, wm, wn, lane);

    float* gbuf = (float*)sm;
    store_gbuf(gbuf, d, wm, wn, lane);
    __syncthreads();

    // cell update: thread -> (row, 8 consecutive u)
    {
        int row = tid >> 2, ub = (tid & 3) * 8;
        float xi = xs[row];
        size_t rowbase = (size_t)(b0 + row) * HD + u0 + ub;
        float4 ca = *(const float4*)(g_c1 + rowbase);
        float4 cb = *(const float4*)(g_c1 + rowbase + 4);
        float cv[8] = {ca.x, ca.y, ca.z, ca.w, cb.x, cb.y, cb.z, cb.w};
        __align__(16) __half hq[8];
        #pragma unroll
        for (int j = 0; j < 8; j++) {
            int ul = ub + j;
            int ug = u0 + ul;
            float iv = gbuf[row * 132 + ul]       + g_b0[ug]          + xi * w_ih0[ug];
            float fv = gbuf[row * 132 + 32 + ul]  + g_b0[HD + ug]     + xi * w_ih0[HD + ug];
            float gv = gbuf[row * 132 + 64 + ul]  + g_b0[2*HD + ug]   + xi * w_ih0[2*HD + ug];
            float ov = gbuf[row * 132 + 96 + ul]  + g_b0[3*HD + ug]   + xi * w_ih0[3*HD + ug];
            float cn = sigf(fv) * cv[j] + sigf(iv) * tanhsf(gv);
            cv[j] = cn;
            float h = sigf(ov) * tanhsf(cn);
            hq[j] = __float2half_rn(h);
        }
        *(float4*)(g_c1 + rowbase)     = make_float4(cv[0], cv[1], cv[2], cv[3]);
        *(float4*)(g_c1 + rowbase + 4) = make_float4(cv[4], cv[5], cv[6], cv[7]);
        *(uint4*)(g_h1q[rd ^ 1] + rowbase) = *(const uint4*)hq;
    }
}

// ---------------- phase B: layer-1 step (K=1024, two segments) ----------------
__global__ void __launch_bounds__(256) phaseB_k(int rd)
{
    extern __shared__ char sm[];
    uint32_t sb = smem_u32(sm);
    const int tid = threadIdx.x, lane = tid & 31, wid = tid >> 5;
    const int wm = wid >> 2, wn = wid & 3;
    const int b0 = blockIdx.x * MB, u0 = blockIdx.y * NU;

    const __half* As[2] = { g_h1q[rd ^ 1], g_h2q[rd] };
    const __half* Ws[2] = { g_wih1, g_whh1 };

    stage_load(sb, As[0], Ws[0], b0, u0, 0, tid);
    CP_COMMIT();
    stage_load(sb + STAGE_BYTES, As[0], Ws[0], b0, u0, KC, tid);
    CP_COMMIT();

    float d[2][4][4] = {};
    run_pipeline<16>(sb, As, Ws, b0, u0, tid, d, wm, wn, lane);

    float* gbuf = (float*)sm;
    store_gbuf(gbuf, d, wm, wn, lane);
    __syncthreads();

    {
        int row = tid >> 2, ub = (tid & 3) * 8;
        size_t rowbase = (size_t)(b0 + row) * HD + u0 + ub;
        float4 ca = *(const float4*)(g_c2 + rowbase);
        float4 cb = *(const float4*)(g_c2 + rowbase + 4);
        float cv[8] = {ca.x, ca.y, ca.z, ca.w, cb.x, cb.y, cb.z, cb.w};
        float hv[8];
        __align__(16) __half hq[8];
        #pragma unroll
        for (int j = 0; j < 8; j++) {
            int ul = ub + j;
            int ug = u0 + ul;
            float iv = gbuf[row * 132 + ul]      + g_b1[ug];
            float fv = gbuf[row * 132 + 32 + ul] + g_b1[HD + ug];
            float gv = gbuf[row * 132 + 64 + ul] + g_b1[2*HD + ug];
            float ov = gbuf[row * 132 + 96 + ul] + g_b1[3*HD + ug];
            float cn = sigf(fv) * cv[j] + sigf(iv) * tanhsf(gv);
            cv[j] = cn;
            float h = sigf(ov) * tanhsf(cn);
            hv[j] = h;
            hq[j] = __float2half_rn(h);
        }
        *(float4*)(g_c2 + rowbase)     = make_float4(cv[0], cv[1], cv[2], cv[3]);
        *(float4*)(g_c2 + rowbase + 4) = make_float4(cv[4], cv[5], cv[6], cv[7]);
        *(float4*)(g_h2f[rd ^ 1] + rowbase)     = make_float4(hv[0], hv[1], hv[2], hv[3]);
        *(float4*)(g_h2f[rd ^ 1] + rowbase + 4) = make_float4(hv[4], hv[5], hv[6], hv[7]);
        *(uint4*)(g_h2q[rd ^ 1] + rowbase) = *(const uint4*)hq;
    }
}

// ---------------- final prediction ----------------
__global__ void __launch_bounds__(256) final_y(
    int rd, const float* __restrict__ w_lin, const float* __restrict__ b_lin,
    float* __restrict__ out)
{
    int tid = threadIdx.x;
    int rrow = blockIdx.x * 128 + (tid >> 1);   // grid 4
    int p = tid & 1;
    const float4* hr = (const float4*)(g_h2f[rd] + (size_t)rrow * HD);
    const float4* wl = (const float4*)w_lin;
    float s = 0.f;
    #pragma unroll 16
    for (int kk = p; kk < HD / 4; kk += 2) {
        float4 a = hr[kk]; float4 w = wl[kk];
        s += a.x * w.x + a.y * w.y + a.z * w.z + a.w * w.w;
    }
    s += __shfl_xor_sync(0xffffffffu, s, 1);
    if (p == 0) out[(size_t)rrow * TD + (TD - 1)] = s + b_lin[0];
}

// ---------------- host launcher ----------------
extern "C" void kernel_launch(void* const* d_in, const int* in_sizes, int n_in,
                              void* d_out, int out_size)
{
    const float* x     = (const float*)d_in[0];
    const float* w_ih0 = (const float*)d_in[3];
    const float* w_hh0 = (const float*)d_in[4];
    const float* b_ih0 = (const float*)d_in[5];
    const float* b_hh0 = (const float*)d_in[6];
    const float* w_ih1 = (const float*)d_in[7];
    const float* w_hh1 = (const float*)d_in[8];
    const float* b_ih1 = (const float*)d_in[9];
    const float* b_hh1 = (const float*)d_in[10];
    const float* w_lin = (const float*)d_in[11];
    const float* b_lin = (const float*)d_in[12];
    float* out = (float*)d_out;

    cudaFuncSetAttribute(phaseA_k, cudaFuncAttributeMaxDynamicSharedMemorySize, SMEM_TOTAL);
    cudaFuncSetAttribute(phaseB_k, cudaFuncAttributeMaxDynamicSharedMemorySize, SMEM_TOTAL);

    zero_state<<<1024, 256>>>();
    prep_bias<<<8, 256>>>(b_ih0, b_hh0, b_ih1, b_hh1);
    quantw1<<<4096, 256>>>(w_hh0, 0);
    quantw1<<<4096, 256>>>(w_ih1, 1);
    quantw1<<<4096, 256>>>(w_hh1, 2);

    dim3 grid(BD / MB, HD / NU);   // (8, 16) = 128 CTAs
    int s = 0;
    for (int t = 0; t < TD; ++t, ++s) {
        phaseA_k<<<grid, 256, SMEM_TOTAL>>>(s & 1, x, t, 0,
                                            nullptr, nullptr, nullptr, 0, w_ih0);
        phaseB_k<<<grid, 256, SMEM_TOTAL>>>(s & 1);
    }
    for (int i = 1; i < TD; ++i, ++s) {
        phaseA_k<<<grid, 256, SMEM_TOTAL>>>(s & 1, nullptr, 0, (i == 1) ? 1 : 0,
                                            w_lin, b_lin, out, i - 1, w_ih0);
        phaseB_k<<<grid, 256, SMEM_TOTAL>>>(s & 1);
    }
    final_y<<<4, 256>>>(s & 1, w_lin, b_lin, out);
}

// round 14
// speedup vs baseline: 1.0608x; 1.0608x over previous
#include <cuda_runtime.h>
#include <cuda_fp16.h>
#include <stdint.h>
#include <math.h>

// ---------------- dims ----------------
#define HD 512
#define BD 512
#define TD 128
#define NSTEP (2 * TD - 1)   // 255 steps total

#define MB 64        // batch rows per CTA (M)
#define NU 32        // units per CTA; N = 4 gates x 32 = 128
#define KC 64        // k per stage
#define NBLK 128     // persistent grid size (<=148 SMs, 1 CTA/SM)

// smem stage layout: rows padded to 144B (64 fp16 = 128B data + 16B pad)
#define ROWB 144
#define A_BYTES (64 * ROWB)                 // 9216
#define W_BYTES (128 * ROWB)                // 18432
#define OFF_WHI A_BYTES
#define OFF_WLO (A_BYTES + W_BYTES)
#define STAGE_BYTES (A_BYTES + 2 * W_BYTES) // 46080
#define NSTG 4
#define OFF_GBUF (NSTG * STAGE_BYTES)       // 184320 (gbuf no longer aliases stages)
#define GBUF_BYTES (64 * 132 * 4)           // 33792
#define OFF_XS (OFF_GBUF + GBUF_BYTES)      // 218112
#define SMEM_TOTAL (OFF_XS + 512)           // 218624

// ---------------- persistent device state ----------------
__device__ float g_h2f[BD*HD];              // h2 fp32 (for y head), single buffer
__device__ float g_c2f[BD*HD];              // c2 fp32 copy (only for first AR y)
__device__ __align__(16) __half g_h1q[2][BD*HD];
__device__ __align__(16) __half g_h2q[2][BD*HD];
__device__ float g_b0[4*HD], g_b1[4*HD];
__device__ __align__(16) __half g_whh0a[4*HD*HD], g_whh0b[4*HD*HD];
__device__ __align__(16) __half g_wih1a[4*HD*HD], g_wih1b[4*HD*HD];
__device__ __align__(16) __half g_whh1a[4*HD*HD], g_whh1b[4*HD*HD];
__device__ unsigned g_count;
__device__ unsigned g_gen;

// ---------------- helpers ----------------
__device__ __forceinline__ uint32_t smem_u32(const void* p) {
    uint32_t a;
    asm("{ .reg .u64 t; cvta.to.shared.u64 t, %1; cvt.u32.u64 %0, t; }" : "=r"(a) : "l"(p));
    return a;
}
__device__ __forceinline__ void cpa16(uint32_t dst, const void* src) {
    asm volatile("cp.async.cg.shared.global [%0], [%1], 16;" :: "r"(dst), "l"(src));
}
#define CP_COMMIT() asm volatile("cp.async.commit_group;")
#define CP_WAIT(n)  asm volatile("cp.async.wait_group %0;" :: "n"(n))

__device__ __forceinline__ void ldm4(uint32_t (&r)[4], uint32_t addr) {
    asm volatile("ldmatrix.sync.aligned.m8n8.x4.shared.b16 {%0,%1,%2,%3}, [%4];"
        : "=r"(r[0]), "=r"(r[1]), "=r"(r[2]), "=r"(r[3]) : "r"(addr));
}
__device__ __forceinline__ void mma_f16(float (&d)[4], const uint32_t a[4], const uint32_t b[2]) {
    asm volatile("mma.sync.aligned.m16n8k16.row.col.f32.f16.f16.f32 "
        "{%0,%1,%2,%3}, {%4,%5,%6,%7}, {%8,%9}, {%0,%1,%2,%3};"
        : "+f"(d[0]), "+f"(d[1]), "+f"(d[2]), "+f"(d[3])
        : "r"(a[0]), "r"(a[1]), "r"(a[2]), "r"(a[3]), "r"(b[0]), "r"(b[1]));
}

__device__ __forceinline__ float sigf(float z) { return 1.0f / (1.0f + __expf(-z)); }
__device__ __forceinline__ float tanhsf(float z) {
    float e = __expf(2.0f * z);
    return 1.0f - 2.0f / (e + 1.0f);
}

// grid-wide barrier: all NBLK CTAs resident (1/SM). target = expected gen value.
__device__ __forceinline__ void grid_bar(unsigned target) {
    __syncthreads();
    if (threadIdx.x == 0) {
        __threadfence();
        unsigned a = atomicAdd(&g_count, 1);
        if (a == NBLK - 1) {
            g_count = 0;           // all arrived; none can re-arrive before gen bump
            __threadfence();
            atomicAdd(&g_gen, 1);
        } else {
            while (*((volatile unsigned*)&g_gen) < target) __nanosleep(64);
        }
    }
    __syncthreads();
}

// ---------------- loaders ----------------
__device__ __forceinline__ void load_W_stage(uint32_t st,
    const __half* __restrict__ whi, const __half* __restrict__ wlo,
    int u0, int k0, int tid)
{
    #pragma unroll
    for (int q = 0; q < 4; q++) {
        int i = tid + q * 256;
        int n = i >> 3, s = (i & 7) * 8;
        int wrow = ((n >> 5) << 9) + u0 + (n & 31);  // gate*512 + u
        uint32_t doff = (uint32_t)(n * ROWB + s * 2);
        size_t goff = (size_t)wrow * HD + k0 + s;
        cpa16(st + OFF_WHI + doff, whi + goff);
        cpa16(st + OFF_WLO + doff, wlo + goff);
    }
}
__device__ __forceinline__ void load_A_stage(uint32_t st,
    const __half* __restrict__ a, int b0, int k0, int tid)
{
    #pragma unroll
    for (int q = 0; q < 2; q++) {
        int i = tid + q * 256;
        int r = i >> 3, s = (i & 7) * 8;
        uint32_t doff = (uint32_t)(r * ROWB + s * 2);
        size_t goff = (size_t)(b0 + r) * HD + k0 + s;
        cpa16(st + doff, a + goff);
    }
}
__device__ __forceinline__ void stage_load(uint32_t st,
    const __half* __restrict__ a,
    const __half* __restrict__ whi, const __half* __restrict__ wlo,
    int b0, int u0, int k0, int tid)
{
    load_A_stage(st, a, b0, k0, tid);
    load_W_stage(st, whi, wlo, u0, k0, tid);
}

// ---------------- compute one 64-k stage: 2 products into d ----------------
__device__ __forceinline__ void compute_stage(uint32_t sbase, float (&d)[2][4][4],
                                              int wm, int wn, int lane)
{
    const int l7 = lane & 7, grp = lane >> 3;
    const uint32_t a_row = (uint32_t)(((grp & 1) << 3) + l7);
    const uint32_t a_kb  = (uint32_t)((grp >> 1) << 4);
    const uint32_t b_n   = (uint32_t)(((grp >> 1) << 3) + l7);
    const uint32_t b_kb  = (uint32_t)((grp & 1) << 4);

    #pragma unroll
    for (int kk = 0; kk < 4; kk++) {
        uint32_t kb = kk * 32;
        uint32_t Ah[2][4], Bh[2][4], Bl[2][4];
        #pragma unroll
        for (int mi = 0; mi < 2; mi++) {
            uint32_t ra = sbase + (wm * 32 + mi * 16 + a_row) * ROWB + kb + a_kb;
            ldm4(Ah[mi], ra);
        }
        #pragma unroll
        for (int p = 0; p < 2; p++) {
            uint32_t rb = sbase + OFF_WHI + (wn * 32 + p * 16 + b_n) * ROWB + kb + b_kb;
            ldm4(Bh[p], rb);
            ldm4(Bl[p], rb + W_BYTES);
        }
        #pragma unroll
        for (int mi = 0; mi < 2; mi++) {
            #pragma unroll
            for (int ni = 0; ni < 4; ni++) {
                const uint32_t* bh = &Bh[ni >> 1][(ni & 1) * 2];
                const uint32_t* bl = &Bl[ni >> 1][(ni & 1) * 2];
                mma_f16(d[mi][ni], Ah[mi], bh);
                mma_f16(d[mi][ni], Ah[mi], bl);
            }
        }
    }
}

__device__ __forceinline__ void store_gbuf(float* gbuf, float (&d)[2][4][4],
                                           int wm, int wn, int lane)
{
    const int gid = lane >> 2, tig = lane & 3;
    #pragma unroll
    for (int mi = 0; mi < 2; mi++) {
        #pragma unroll
        for (int ni = 0; ni < 4; ni++) {
            int row = wm * 32 + mi * 16 + gid;
            int c0 = wn * 32 + ni * 8 + tig * 2;
            gbuf[row * 132 + c0]           = d[mi][ni][0];
            gbuf[row * 132 + c0 + 1]       = d[mi][ni][1];
            gbuf[(row + 8) * 132 + c0]     = d[mi][ni][2];
            gbuf[(row + 8) * 132 + c0 + 1] = d[mi][ni][3];
        }
    }
}

// ---------------- pipeline: caller pre-issued groups W0,W1,A0,A1 ----------------
// Group order Ga(W0),Gb(W1),Gc(A0),Gd(A1) then full stages j=2.. => in-loop
// CP_WAIT(2) guarantees stage i fully loaded before compute i (verified).
template<int NS>
__device__ __forceinline__ void run_pipeline(
    uint32_t sb,
    const __half* const* As,
    const __half* const* WHs, const __half* const* WLs,
    int b0, int u0, int tid,
    float (&d)[2][4][4], int wm, int wn, int lane)
{
    #pragma unroll 1
    for (int i = 0; i < NS; i++) {
        if (i + 2 < NS) {
            int j = i + 2, sg = j >> 3;
            stage_load(sb + (j % NSTG) * STAGE_BYTES, As[sg], WHs[sg], WLs[sg],
                       b0, u0, (j & 7) * KC, tid);
            CP_COMMIT();
            CP_WAIT(2);
        } else {
            CP_WAIT(0);
        }
        __syncthreads();
        compute_stage(sb + (i % NSTG) * STAGE_BYTES, d, wm, wn, lane);
    }
    __syncthreads();
}

// ---------------- setup kernels ----------------
__global__ void __launch_bounds__(256) zero_state() {
    int idx = blockIdx.x * 256 + threadIdx.x;   // grid 1024 -> 262144
    __half z = __float2half(0.f);
    g_h1q[0][idx] = z; g_h2q[0][idx] = z;
    if (idx == 0) { g_count = 0; g_gen = 0; }
}
__global__ void __launch_bounds__(256) prep_bias(
    const float* __restrict__ b_ih0, const float* __restrict__ b_hh0,
    const float* __restrict__ b_ih1, const float* __restrict__ b_hh1) {
    int j = blockIdx.x * 256 + threadIdx.x;     // grid 8
    g_b0[j] = b_ih0[j] + b_hh0[j];
    g_b1[j] = b_ih1[j] + b_hh1[j];
}
__global__ void __launch_bounds__(256) splitw(const float* __restrict__ w, int which) {
    __half *hi, *lo;
    if (which == 0)      { hi = g_whh0a; lo = g_whh0b; }
    else if (which == 1) { hi = g_wih1a; lo = g_wih1b; }
    else                 { hi = g_whh1a; lo = g_whh1b; }
    int i = blockIdx.x * 256 + threadIdx.x;     // grid 4096
    float v = w[i];
    __half h = __float2half_rn(v);
    hi[i] = h;
    lo[i] = __float2half_rn(v - __half2float(h));
}

// ---------------- the persistent kernel ----------------
__global__ void __launch_bounds__(256) lstm_persist(
    const float* __restrict__ xin,
    const float* __restrict__ w_ih0,
    const float* __restrict__ w_lin, const float* __restrict__ b_lin,
    float* __restrict__ out)
{
    extern __shared__ char sm[];
    uint32_t sb = smem_u32(sm);
    const int tid = threadIdx.x, lane = tid & 31, wid = tid >> 5;
    const int wm = wid >> 2, wn = wid & 3;
    const int bid = blockIdx.x;
    const int b0 = (bid & 7) * MB;        // 8 M-tiles
    const int u0 = (bid >> 3) * NU;       // 16 N-tiles
    const int is_out_cta = ((bid >> 3) == 0);
    float* gbuf = (float*)(sm + OFF_GBUF);
    float* xs = (float*)(sm + OFF_XS);

    float cv1[8], cv2[8];
    #pragma unroll
    for (int j = 0; j < 8; j++) { cv1[j] = 0.f; cv2[j] = 0.f; }

    const int erow = tid >> 2, eub = (tid & 3) * 8;   // epilogue mapping
    unsigned bar = 0;

    #pragma unroll 1
    for (int s = 0; s < NSTEP; s++) {
        const int rd = s & 1;

        // ======== phase A ========
        const __half* AsA[2] = { g_h1q[rd], g_h1q[rd] };
        const __half* WHA[2] = { g_whh0a, g_whh0a };
        const __half* WLA[2] = { g_whh0b, g_whh0b };
        if (s == 0) {   // later steps: W prefetched in previous B-epilogue
            load_W_stage(sb, g_whh0a, g_whh0b, u0, 0, tid);  CP_COMMIT();
            load_W_stage(sb + STAGE_BYTES, g_whh0a, g_whh0b, u0, KC, tid); CP_COMMIT();
        }
        load_A_stage(sb, g_h1q[rd], b0, 0, tid);  CP_COMMIT();
        load_A_stage(sb + STAGE_BYTES, g_h1q[rd], b0, KC, tid); CP_COMMIT();

        // input scalar per batch row
        if (s < TD) {
            if (tid < MB) xs[tid] = xin[(size_t)(b0 + tid) * TD + s];
        } else {
            const float* ysrc = (s == TD) ? g_c2f : g_h2f;
            int rrow = tid >> 2, p = tid & 3;
            const float4* hr = (const float4*)(ysrc + (size_t)(b0 + rrow) * HD);
            const float4* wl = (const float4*)w_lin;
            float acc = 0.f;
            #pragma unroll 8
            for (int kk = p; kk < HD / 4; kk += 4) {
                float4 a = __ldcg(hr + kk); float4 w = wl[kk];
                acc += a.x * w.x + a.y * w.y + a.z * w.z + a.w * w.w;
            }
            acc += __shfl_xor_sync(0xffffffffu, acc, 1);
            acc += __shfl_xor_sync(0xffffffffu, acc, 2);
            if (p == 0) {
                float yv = acc + b_lin[0];
                xs[rrow] = yv;
                if (is_out_cta) out[(size_t)(b0 + rrow) * TD + (s - TD)] = yv;
            }
        }

        float d[2][4][4] = {};
        run_pipeline<8>(sb, AsA, WHA, WLA, b0, u0, tid, d, wm, wn, lane);

        // prefetch W for phase B stages 0,1 (overlaps epilogue + barrier)
        load_W_stage(sb, g_wih1a, g_wih1b, u0, 0, tid);  CP_COMMIT();
        load_W_stage(sb + STAGE_BYTES, g_wih1a, g_wih1b, u0, KC, tid); CP_COMMIT();

        store_gbuf(gbuf, d, wm, wn, lane);
        __syncthreads();
        {   // cell update layer 0 (c1 in registers)
            float xi = xs[erow];
            size_t rowbase = (size_t)(b0 + erow) * HD + u0 + eub;
            __align__(16) __half hq[8];
            #pragma unroll
            for (int j = 0; j < 8; j++) {
                int ul = eub + j, ug = u0 + ul;
                float iv = gbuf[erow * 132 + ul]      + g_b0[ug]        + xi * w_ih0[ug];
                float fv = gbuf[erow * 132 + 32 + ul] + g_b0[HD + ug]   + xi * w_ih0[HD + ug];
                float gv = gbuf[erow * 132 + 64 + ul] + g_b0[2*HD + ug] + xi * w_ih0[2*HD + ug];
                float ov = gbuf[erow * 132 + 96 + ul] + g_b0[3*HD + ug] + xi * w_ih0[3*HD + ug];
                float cn = sigf(fv) * cv1[j] + sigf(iv) * tanhsf(gv);
                cv1[j] = cn;
                hq[j] = __float2half_rn(sigf(ov) * tanhsf(cn));
            }
            *(uint4*)(g_h1q[rd ^ 1] + rowbase) = *(const uint4*)hq;
        }
        bar++; grid_bar(bar);

        // ======== phase B ========
        const __half* AsB[2] = { g_h1q[rd ^ 1], g_h2q[rd] };
        const __half* WHB[2] = { g_wih1a, g_whh1a };
        const __half* WLB[2] = { g_wih1b, g_whh1b };
        load_A_stage(sb, g_h1q[rd ^ 1], b0, 0, tid);  CP_COMMIT();
        load_A_stage(sb + STAGE_BYTES, g_h1q[rd ^ 1], b0, KC, tid); CP_COMMIT();

        float d2[2][4][4] = {};
        run_pipeline<16>(sb, AsB, WHB, WLB, b0, u0, tid, d2, wm, wn, lane);

        // prefetch W for next step's phase A (skip on last step)
        if (s + 1 < NSTEP) {
            load_W_stage(sb, g_whh0a, g_whh0b, u0, 0, tid);  CP_COMMIT();
            load_W_stage(sb + STAGE_BYTES, g_whh0a, g_whh0b, u0, KC, tid); CP_COMMIT();
        }

        store_gbuf(gbuf, d2, wm, wn, lane);
        __syncthreads();
        {   // cell update layer 1 (c2 in registers)
            size_t rowbase = (size_t)(b0 + erow) * HD + u0 + eub;
            float hv[8];
            __align__(16) __half hq[8];
            #pragma unroll
            for (int j = 0; j < 8; j++) {
                int ul = eub + j, ug = u0 + ul;
                float iv = gbuf[erow * 132 + ul]      + g_b1[ug];
                float fv = gbuf[erow * 132 + 32 + ul] + g_b1[HD + ug];
                float gv = gbuf[erow * 132 + 64 + ul] + g_b1[2*HD + ug];
                float ov = gbuf[erow * 132 + 96 + ul] + g_b1[3*HD + ug];
                float cn = sigf(fv) * cv2[j] + sigf(iv) * tanhsf(gv);
                cv2[j] = cn;
                float h = sigf(ov) * tanhsf(cn);
                hv[j] = h;
                hq[j] = __float2half_rn(h);
            }
            *(float4*)(g_h2f + rowbase)     = make_float4(hv[0], hv[1], hv[2], hv[3]);
            *(float4*)(g_h2f + rowbase + 4) = make_float4(hv[4], hv[5], hv[6], hv[7]);
            if (s == TD - 1) {   // c2 snapshot only needed for first AR y
                *(float4*)(g_c2f + rowbase)     = make_float4(cv2[0], cv2[1], cv2[2], cv2[3]);
                *(float4*)(g_c2f + rowbase + 4) = make_float4(cv2[4], cv2[5], cv2[6], cv2[7]);
            }
            *(uint4*)(g_h2q[rd ^ 1] + rowbase) = *(const uint4*)hq;
        }
        bar++; grid_bar(bar);
    }

    // final prediction y_{T-1} -> out[:, TD-1]
    if (is_out_cta) {
        int rrow = tid >> 2, p = tid & 3;
        const float4* hr = (const float4*)(g_h2f + (size_t)(b0 + rrow) * HD);
        const float4* wl = (const float4*)w_lin;
        float acc = 0.f;
        #pragma unroll 8
        for (int kk = p; kk < HD / 4; kk += 4) {
            float4 a = __ldcg(hr + kk); float4 w = wl[kk];
            acc += a.x * w.x + a.y * w.y + a.z * w.z + a.w * w.w;
        }
        acc += __shfl_xor_sync(0xffffffffu, acc, 1);
        acc += __shfl_xor_sync(0xffffffffu, acc, 2);
        if (p == 0) out[(size_t)(b0 + rrow) * TD + (TD - 1)] = acc + b_lin[0];
    }
}

// ---------------- host launcher ----------------
extern "C" void kernel_launch(void* const* d_in, const int* in_sizes, int n_in,
                              void* d_out, int out_size)
{
    const float* x     = (const float*)d_in[0];
    const float* w_ih0 = (const float*)d_in[3];
    const float* w_hh0 = (const float*)d_in[4];
    const float* b_ih0 = (const float*)d_in[5];
    const float* b_hh0 = (const float*)d_in[6];
    const float* w_ih1 = (const float*)d_in[7];
    const float* w_hh1 = (const float*)d_in[8];
    const float* b_ih1 = (const float*)d_in[9];
    const float* b_hh1 = (const float*)d_in[10];
    const float* w_lin = (const float*)d_in[11];
    const float* b_lin = (const float*)d_in[12];
    float* out = (float*)d_out;

    cudaFuncSetAttribute(lstm_persist, cudaFuncAttributeMaxDynamicSharedMemorySize, SMEM_TOTAL);

    zero_state<<<1024, 256>>>();
    prep_bias<<<8, 256>>>(b_ih0, b_hh0, b_ih1, b_hh1);
    splitw<<<4096, 256>>>(w_hh0, 0);
    splitw<<<4096, 256>>>(w_ih1, 1);
    splitw<<<4096, 256>>>(w_hh1, 2);

    lstm_persist<<<NBLK, 256, SMEM_TOTAL>>>(x, w_ih0, w_lin, b_lin, out);
}